// round 1
// baseline (speedup 1.0000x reference)
#include <cuda_runtime.h>
#include <math.h>

// Problem constants (from reference): B=32, T=1024, D=256, H=256
#define BB 32
#define TT 1024
#define DD 256
#define HH 256
#define SPLIT 8            // T-splits for the c reduction
#define TCHUNK (TT / SPLIT)  // 128

// Scratch (device globals — no allocation allowed)
__device__ __align__(16) float g_partial[BB * SPLIT * DD];
__device__ __align__(16) float g_W[BB * DD];
__device__ __align__(16) float g_bias[BB * DD];

// ---------------------------------------------------------------------------
// Kernel A: partial sums of x over T  ->  g_partial[b][s][d]
// grid = B*SPLIT blocks, 256 threads (one per d). Coalesced: consecutive
// threads read consecutive d.
// ---------------------------------------------------------------------------
__global__ void reduce_c_kernel(const float* __restrict__ x) {
    int blk = blockIdx.x;
    int b = blk / SPLIT;
    int s = blk % SPLIT;
    int d = threadIdx.x;
    const float* xp = x + ((size_t)b * TT + (size_t)s * TCHUNK) * DD + d;
    float sum = 0.0f;
#pragma unroll 8
    for (int t = 0; t < TCHUNK; t++) {
        sum += xp[(size_t)t * DD];
    }
    g_partial[(b * SPLIT + s) * DD + d] = sum;
}

// ---------------------------------------------------------------------------
// Kernel B: per-batch MLPs.
//   c[d] = (sum_t x[b,t,d]) / len[b]
//   h = gelu(c @ W1^T + b1)   (exact gelu, erf)
//   out = h @ W2^T + b2
// Computed twice (W-branch and bias-branch). grid = B, 256 threads.
// ---------------------------------------------------------------------------
__device__ __forceinline__ float gelu_exact(float v) {
    return 0.5f * v * (1.0f + erff(v * 0.70710678118654752f));
}

__global__ void mlp_kernel(const int* __restrict__ len,
                           const float* __restrict__ w1w, const float* __restrict__ w1b,
                           const float* __restrict__ w2w, const float* __restrict__ w2b,
                           const float* __restrict__ q1w, const float* __restrict__ q1b,
                           const float* __restrict__ q2w, const float* __restrict__ q2b) {
    __shared__ float c_sh[DD];
    __shared__ float h_sh[HH];

    int b = blockIdx.x;
    int j = threadIdx.x;

    // reduce partials -> c
    float s = 0.0f;
#pragma unroll
    for (int p = 0; p < SPLIT; p++) s += g_partial[(b * SPLIT + p) * DD + j];
    c_sh[j] = s / (float)len[b];
    __syncthreads();

    // --- W branch ---
    {
        float acc = w1b[j];
        const float* row = w1w + (size_t)j * DD;
#pragma unroll 8
        for (int d = 0; d < DD; d++) acc = fmaf(c_sh[d], row[d], acc);
        h_sh[j] = gelu_exact(acc);
    }
    __syncthreads();
    {
        float acc = w2b[j];
        const float* row = w2w + (size_t)j * HH;
#pragma unroll 8
        for (int h = 0; h < HH; h++) acc = fmaf(h_sh[h], row[h], acc);
        g_W[b * DD + j] = acc;
    }
    __syncthreads();

    // --- bias branch (reuse h_sh) ---
    {
        float acc = q1b[j];
        const float* row = q1w + (size_t)j * DD;
#pragma unroll 8
        for (int d = 0; d < DD; d++) acc = fmaf(c_sh[d], row[d], acc);
        h_sh[j] = gelu_exact(acc);
    }
    __syncthreads();
    {
        float acc = q2b[j];
        const float* row = q2w + (size_t)j * HH;
#pragma unroll 8
        for (int h = 0; h < HH; h++) acc = fmaf(h_sh[h], row[h], acc);
        g_bias[b * DD + j] = acc;
    }
}

// ---------------------------------------------------------------------------
// Kernel C: elementwise apply (float4 vectorized)
//   out[b,t,d] = t < L ? x*(1+W[b,d]) + (t==0)*bias[b,d] : 0
// total float4 elements = B*T*D/4 = 2,097,152
// ---------------------------------------------------------------------------
__global__ void apply_kernel(const float* __restrict__ x,
                             const int* __restrict__ len,
                             float* __restrict__ out) {
    size_t i = (size_t)blockIdx.x * blockDim.x + threadIdx.x;
    // i is a float4 index
    int d4 = (int)(i & 63);           // D/4 = 64
    int t  = (int)((i >> 6) & 1023);  // T = 1024
    int b  = (int)(i >> 16);          // 64*1024 per batch

    float4 xv = reinterpret_cast<const float4*>(x)[i];
    int L = __ldg(&len[b]);

    float4 o;
    if (t < L) {
        float4 wv = reinterpret_cast<const float4*>(g_W)[b * 64 + d4];
        o.x = xv.x * (1.0f + wv.x);
        o.y = xv.y * (1.0f + wv.y);
        o.z = xv.z * (1.0f + wv.z);
        o.w = xv.w * (1.0f + wv.w);
        if (t == 0) {
            float4 bv = reinterpret_cast<const float4*>(g_bias)[b * 64 + d4];
            o.x += bv.x; o.y += bv.y; o.z += bv.z; o.w += bv.w;
        }
    } else {
        o.x = 0.0f; o.y = 0.0f; o.z = 0.0f; o.w = 0.0f;
    }
    reinterpret_cast<float4*>(out)[i] = o;
}

// ---------------------------------------------------------------------------
extern "C" void kernel_launch(void* const* d_in, const int* in_sizes, int n_in,
                              void* d_out, int out_size) {
    const float* x     = (const float*)d_in[0];
    const int*   len_x = (const int*)d_in[1];
    const float* Ww1_w = (const float*)d_in[2];
    const float* Ww1_b = (const float*)d_in[3];
    const float* Ww2_w = (const float*)d_in[4];
    const float* Ww2_b = (const float*)d_in[5];
    const float* Wb1_w = (const float*)d_in[6];
    const float* Wb1_b = (const float*)d_in[7];
    const float* Wb2_w = (const float*)d_in[8];
    const float* Wb2_b = (const float*)d_in[9];
    float* out = (float*)d_out;

    reduce_c_kernel<<<BB * SPLIT, DD>>>(x);
    mlp_kernel<<<BB, DD>>>(len_x, Ww1_w, Ww1_b, Ww2_w, Ww2_b,
                           Wb1_w, Wb1_b, Wb2_w, Wb2_b);
    const size_t total4 = (size_t)BB * TT * DD / 4;  // 2,097,152
    apply_kernel<<<(unsigned)(total4 / 256), 256>>>(x, len_x, out);
}

// round 2
// speedup vs baseline: 3.4132x; 3.4132x over previous
#include <cuda_runtime.h>
#include <math.h>

// Problem constants: B=32, T=1024, D=256, H=256
#define BB 32
#define TT 1024
#define DD 256
#define HH 256
#define SPLIT 32
#define TCHUNK (TT / SPLIT)   // 32 rows per reduce block

// Scratch (device globals — no allocation allowed)
__device__ __align__(16) float g_partial[BB * SPLIT * DD];   // 4 MB
__device__ __align__(16) float g_W[BB * DD];
__device__ __align__(16) float g_bias[BB * DD];

// ---------------------------------------------------------------------------
// Kernel A: partial sums of x over T -> g_partial[b][s][d], float4 vectorized.
// grid = B*SPLIT = 1024 blocks, 256 threads = 4 t-lanes x 64 d4-lanes.
// ---------------------------------------------------------------------------
__global__ void reduce_c_kernel(const float4* __restrict__ x4) {
    int blk = blockIdx.x;
    int b = blk >> 5;            // / SPLIT
    int s = blk & 31;            // % SPLIT
    int d4 = threadIdx.x & 63;   // 64 float4 per row
    int lt = threadIdx.x >> 6;   // 0..3 t-lane

    // row stride in float4 units = DD/4 = 64
    size_t base = ((size_t)b * TT + (size_t)s * TCHUNK + lt) * 64 + d4;
    float4 acc = make_float4(0.f, 0.f, 0.f, 0.f);
#pragma unroll
    for (int i = 0; i < TCHUNK / 4; i++) {           // 8 iterations
        float4 v = x4[base + (size_t)i * 4 * 64];
        acc.x += v.x; acc.y += v.y; acc.z += v.z; acc.w += v.w;
    }

    __shared__ float4 sm[4][64];
    sm[lt][d4] = acc;
    __syncthreads();
    if (lt == 0) {
        float4 a = sm[0][d4];
        float4 v1 = sm[1][d4], v2 = sm[2][d4], v3 = sm[3][d4];
        a.x += v1.x + v2.x + v3.x;
        a.y += v1.y + v2.y + v3.y;
        a.z += v1.z + v2.z + v3.z;
        a.w += v1.w + v2.w + v3.w;
        reinterpret_cast<float4*>(g_partial)[(size_t)(b * SPLIT + s) * 64 + d4] = a;
    }
}

// ---------------------------------------------------------------------------
// Kernel B: per-batch MLPs, warp-per-output coalesced.
// grid = 2*B = 64 blocks: block (2b+branch). 256 threads = 8 warps.
// Each warp computes 32 outputs; lanes stride d -> coalesced weight reads.
// ---------------------------------------------------------------------------
__device__ __forceinline__ float gelu_exact(float v) {
    return 0.5f * v * (1.0f + erff(v * 0.70710678118654752f));
}

__global__ void mlp_kernel(const int* __restrict__ len,
                           const float* __restrict__ w1w, const float* __restrict__ w1b,
                           const float* __restrict__ w2w, const float* __restrict__ w2b,
                           const float* __restrict__ q1w, const float* __restrict__ q1b,
                           const float* __restrict__ q2w, const float* __restrict__ q2b) {
    __shared__ float c_sh[DD];
    __shared__ float h_sh[HH];

    int b = blockIdx.x >> 1;
    int branch = blockIdx.x & 1;
    const float* m1w = branch ? q1w : w1w;
    const float* m1b = branch ? q1b : w1b;
    const float* m2w = branch ? q2w : w2w;
    const float* m2b = branch ? q2b : w2b;
    float* gout = branch ? g_bias : g_W;

    int j = threadIdx.x;
    // reduce partials -> c (coalesced over j)
    float s = 0.0f;
#pragma unroll 8
    for (int p = 0; p < SPLIT; p++) s += g_partial[(size_t)(b * SPLIT + p) * DD + j];
    c_sh[j] = s / (float)len[b];
    __syncthreads();

    int w = threadIdx.x >> 5;
    int lane = threadIdx.x & 31;

    // layer 1: h = gelu(c @ W1^T + b1)
    for (int jj = 0; jj < 32; jj++) {
        int o = w * 32 + jj;
        const float* row = m1w + (size_t)o * DD;
        float acc = 0.0f;
#pragma unroll
        for (int i = 0; i < DD / 32; i++)
            acc = fmaf(c_sh[lane + 32 * i], row[lane + 32 * i], acc);
#pragma unroll
        for (int off = 16; off > 0; off >>= 1)
            acc += __shfl_down_sync(0xFFFFFFFFu, acc, off);
        if (lane == 0) h_sh[o] = gelu_exact(acc + m1b[o]);
    }
    __syncthreads();

    // layer 2: out = h @ W2^T + b2
    for (int jj = 0; jj < 32; jj++) {
        int o = w * 32 + jj;
        const float* row = m2w + (size_t)o * HH;
        float acc = 0.0f;
#pragma unroll
        for (int i = 0; i < HH / 32; i++)
            acc = fmaf(h_sh[lane + 32 * i], row[lane + 32 * i], acc);
#pragma unroll
        for (int off = 16; off > 0; off >>= 1)
            acc += __shfl_down_sync(0xFFFFFFFFu, acc, off);
        if (lane == 0) gout[b * DD + o] = acc + m2b[o];
    }
}

// ---------------------------------------------------------------------------
// Kernel C: elementwise apply (float4)
//   out[b,t,d] = t < L ? x*(1+W[b,d]) + (t==0)*bias[b,d] : 0
// ---------------------------------------------------------------------------
__global__ void apply_kernel(const float* __restrict__ x,
                             const int* __restrict__ len,
                             float* __restrict__ out) {
    size_t i = (size_t)blockIdx.x * blockDim.x + threadIdx.x;   // float4 index
    int d4 = (int)(i & 63);
    int t  = (int)((i >> 6) & 1023);
    int b  = (int)(i >> 16);

    float4 xv = reinterpret_cast<const float4*>(x)[i];
    int L = __ldg(&len[b]);

    float4 o;
    if (t < L) {
        float4 wv = reinterpret_cast<const float4*>(g_W)[b * 64 + d4];
        o.x = xv.x * (1.0f + wv.x);
        o.y = xv.y * (1.0f + wv.y);
        o.z = xv.z * (1.0f + wv.z);
        o.w = xv.w * (1.0f + wv.w);
        if (t == 0) {
            float4 bv = reinterpret_cast<const float4*>(g_bias)[b * 64 + d4];
            o.x += bv.x; o.y += bv.y; o.z += bv.z; o.w += bv.w;
        }
    } else {
        o = make_float4(0.f, 0.f, 0.f, 0.f);
    }
    reinterpret_cast<float4*>(out)[i] = o;
}

// ---------------------------------------------------------------------------
extern "C" void kernel_launch(void* const* d_in, const int* in_sizes, int n_in,
                              void* d_out, int out_size) {
    const float* x     = (const float*)d_in[0];
    const int*   len_x = (const int*)d_in[1];
    const float* Ww1_w = (const float*)d_in[2];
    const float* Ww1_b = (const float*)d_in[3];
    const float* Ww2_w = (const float*)d_in[4];
    const float* Ww2_b = (const float*)d_in[5];
    const float* Wb1_w = (const float*)d_in[6];
    const float* Wb1_b = (const float*)d_in[7];
    const float* Wb2_w = (const float*)d_in[8];
    const float* Wb2_b = (const float*)d_in[9];
    float* out = (float*)d_out;

    reduce_c_kernel<<<BB * SPLIT, 256>>>(reinterpret_cast<const float4*>(x));
    mlp_kernel<<<2 * BB, 256>>>(len_x, Ww1_w, Ww1_b, Ww2_w, Ww2_b,
                                Wb1_w, Wb1_b, Wb2_w, Wb2_b);
    const size_t total4 = (size_t)BB * TT * DD / 4;  // 2,097,152
    apply_kernel<<<(unsigned)(total4 / 256), 256>>>(x, len_x, out);
}

// round 3
// speedup vs baseline: 4.1483x; 1.2154x over previous
#include <cuda_runtime.h>
#include <math.h>

// Problem constants: B=32, T=1024, D=256, H=256
#define BB 32
#define TT 1024
#define DD 256
#define HH 256
#define NPART 64            // partials per batch

// Scratch (device globals — no allocation allowed)
__device__ __align__(16) float g_partial[BB * NPART * DD];   // 2 MB
__device__ __align__(16) float g_W[BB * DD];
__device__ __align__(16) float g_bias[BB * DD];

// ---------------------------------------------------------------------------
// Kernel A: partial sums of x over T.
// grid = 1024 blocks x 128 threads. Block (b, s): rows [s*32, s*32+32).
// Thread = (lt in {0,1}, d4 in [0,64)): sums 16 rows (lt, lt+2, ...),
// 16 independent float4 loads. NO block reduce — each lane writes its own
// partial; mlp_kernel absorbs the 64-way reduction.
// ---------------------------------------------------------------------------
__global__ __launch_bounds__(128) void reduce_c_kernel(const float4* __restrict__ x4) {
    int blk = blockIdx.x;
    int b = blk >> 5;            // / 32
    int s = blk & 31;            // % 32
    int d4 = threadIdx.x & 63;
    int lt = threadIdx.x >> 6;   // 0..1

    size_t base = ((size_t)b * TT + (size_t)s * 32 + lt) * 64 + d4;
    float4 acc = make_float4(0.f, 0.f, 0.f, 0.f);
#pragma unroll
    for (int i = 0; i < 16; i++) {
        float4 v = x4[base + (size_t)i * 2 * 64];
        acc.x += v.x; acc.y += v.y; acc.z += v.z; acc.w += v.w;
    }
    // partial index p = s*2 + lt  (0..63)
    reinterpret_cast<float4*>(g_partial)[((size_t)b * NPART + (s * 2 + lt)) * 64 + d4] = acc;
}

// ---------------------------------------------------------------------------
// Kernel B: per-batch MLPs, warp-per-output, float4 weight loads.
// grid = 2*B = 64 blocks (b, branch), 256 threads = 8 warps.
// ---------------------------------------------------------------------------
__device__ __forceinline__ float gelu_exact(float v) {
    return 0.5f * v * (1.0f + erff(v * 0.70710678118654752f));
}

__device__ __forceinline__ float dot4(float4 a, float4 b) {
    return fmaf(a.x, b.x, fmaf(a.y, b.y, fmaf(a.z, b.z, a.w * b.w)));
}

__global__ __launch_bounds__(256) void mlp_kernel(
        const int* __restrict__ len,
        const float* __restrict__ w1w, const float* __restrict__ w1b,
        const float* __restrict__ w2w, const float* __restrict__ w2b,
        const float* __restrict__ q1w, const float* __restrict__ q1b,
        const float* __restrict__ q2w, const float* __restrict__ q2b) {
    __shared__ __align__(16) float c_sh[DD];
    __shared__ __align__(16) float h_sh[HH];

    int b = blockIdx.x >> 1;
    int branch = blockIdx.x & 1;
    const float* m1w = branch ? q1w : w1w;
    const float* m1b = branch ? q1b : w1b;
    const float* m2w = branch ? q2w : w2w;
    const float* m2b = branch ? q2b : w2b;
    float* gout = branch ? g_bias : g_W;

    int j = threadIdx.x;
    // reduce 64 partials -> c (coalesced over j)
    {
        float s = 0.0f;
#pragma unroll 16
        for (int p = 0; p < NPART; p++)
            s += g_partial[((size_t)b * NPART + p) * DD + j];
        c_sh[j] = s / (float)len[b];
    }
    __syncthreads();

    int w = threadIdx.x >> 5;
    int lane = threadIdx.x & 31;
    const float4* c4 = reinterpret_cast<const float4*>(c_sh);
    const float4* h4 = reinterpret_cast<const float4*>(h_sh);

    // layer 1: h = gelu(c @ W1^T + b1); warp computes outputs [w*32, w*32+32)
#pragma unroll 4
    for (int jj = 0; jj < 32; jj++) {
        int o = w * 32 + jj;
        const float4* row = reinterpret_cast<const float4*>(m1w + (size_t)o * DD);
        float acc = dot4(c4[lane], row[lane]) + dot4(c4[lane + 32], row[lane + 32]);
#pragma unroll
        for (int off = 16; off > 0; off >>= 1)
            acc += __shfl_down_sync(0xFFFFFFFFu, acc, off);
        if (lane == 0) h_sh[o] = gelu_exact(acc + m1b[o]);
    }
    __syncthreads();

    // layer 2: out = h @ W2^T + b2
#pragma unroll 4
    for (int jj = 0; jj < 32; jj++) {
        int o = w * 32 + jj;
        const float4* row = reinterpret_cast<const float4*>(m2w + (size_t)o * HH);
        float acc = dot4(h4[lane], row[lane]) + dot4(h4[lane + 32], row[lane + 32]);
#pragma unroll
        for (int off = 16; off > 0; off >>= 1)
            acc += __shfl_down_sync(0xFFFFFFFFu, acc, off);
        if (lane == 0) gout[b * DD + o] = acc + m2b[o];
    }
}

// ---------------------------------------------------------------------------
// Kernel C: elementwise apply.
//   out[b,t,d] = t < L ? x*(1+W[b,d]) + (t==0)*bias[b,d] : 0
// grid = 2048 blocks x 256 threads; thread handles 4 float4 at stride 256.
// Block covers 1024 consecutive float4 (16 KB) => single b per block
// (65536 float4 per batch = 64 blocks/batch).
// ---------------------------------------------------------------------------
__global__ __launch_bounds__(256) void apply_kernel(const float4* __restrict__ x4,
                                                    const int* __restrict__ len,
                                                    float4* __restrict__ out4) {
    size_t base = (size_t)blockIdx.x * 1024;
    int b = (int)(base >> 16);
    int L = __ldg(&len[b]);
    const float4* wv4 = reinterpret_cast<const float4*>(g_W) + b * 64;
    const float4* bv4 = reinterpret_cast<const float4*>(g_bias) + b * 64;

#pragma unroll
    for (int k = 0; k < 4; k++) {
        size_t i = base + threadIdx.x + (size_t)k * 256;
        int d4 = (int)(i & 63);
        int t  = (int)((i >> 6) & 1023);

        float4 xv = x4[i];
        float4 o;
        if (t < L) {
            float4 wv = wv4[d4];
            o.x = fmaf(xv.x, wv.x, xv.x);
            o.y = fmaf(xv.y, wv.y, xv.y);
            o.z = fmaf(xv.z, wv.z, xv.z);
            o.w = fmaf(xv.w, wv.w, xv.w);
            if (t == 0) {
                float4 bv = bv4[d4];
                o.x += bv.x; o.y += bv.y; o.z += bv.z; o.w += bv.w;
            }
        } else {
            o = make_float4(0.f, 0.f, 0.f, 0.f);
        }
        __stcs(&out4[i], o);   // streaming store: don't evict x from L2
    }
}

// ---------------------------------------------------------------------------
extern "C" void kernel_launch(void* const* d_in, const int* in_sizes, int n_in,
                              void* d_out, int out_size) {
    const float* x     = (const float*)d_in[0];
    const int*   len_x = (const int*)d_in[1];
    const float* Ww1_w = (const float*)d_in[2];
    const float* Ww1_b = (const float*)d_in[3];
    const float* Ww2_w = (const float*)d_in[4];
    const float* Ww2_b = (const float*)d_in[5];
    const float* Wb1_w = (const float*)d_in[6];
    const float* Wb1_b = (const float*)d_in[7];
    const float* Wb2_w = (const float*)d_in[8];
    const float* Wb2_b = (const float*)d_in[9];
    float* out = (float*)d_out;

    reduce_c_kernel<<<BB * 32, 128>>>(reinterpret_cast<const float4*>(x));
    mlp_kernel<<<2 * BB, 256>>>(len_x, Ww1_w, Ww1_b, Ww2_w, Ww2_b,
                                Wb1_w, Wb1_b, Wb2_w, Wb2_b);
    apply_kernel<<<2048, 256>>>(reinterpret_cast<const float4*>(x), len_x,
                                reinterpret_cast<float4*>(out));
}